// round 4
// baseline (speedup 1.0000x reference)
#include <cuda_runtime.h>
#include <math_constants.h>

#define D_DIM 4096
#define E_DIM 128
#define BM 64
#define BK 32
#define XS_STRIDE (BM + 4)      // 68
#define WS_STRIDE (E_DIM + 4)   // 132
#define LG_STRIDE (E_DIM + 4)   // 132
#define SMEM_FLOATS (BM * LG_STRIDE)   // 8448 floats = 33792 B (covers GEMM tiles too)

__global__ __launch_bounds__(256, 2)
void gating_fused(const float* __restrict__ x, const float* __restrict__ W,
                  const float* __restrict__ bias, const int* __restrict__ kptr,
                  float* __restrict__ out, int N)
{
    __shared__ float smem[SMEM_FLOATS];
    float* xs = smem;                       // [BK][XS_STRIDE]
    float* ws = smem + BK * XS_STRIDE;      // [BK][WS_STRIDE], ends at 6400 < 8448

    const int tid = threadIdx.x;
    const int tx = tid & 31;   // lane / expert-group
    const int ty = tid >> 5;   // warp / row-group
    const int row0 = blockIdx.x * BM;

    float acc[8][4];
    #pragma unroll
    for (int i = 0; i < 8; i++)
        #pragma unroll
        for (int j = 0; j < 4; j++) acc[i][j] = 0.f;

    for (int k0 = 0; k0 < D_DIM; k0 += BK) {
        // ---- load x tile: 64 rows x 32 k (512 float4, 2 per thread) ----
        #pragma unroll
        for (int it = 0; it < 2; it++) {
            int f = tid + it * 256;
            int r = f >> 3, cg = f & 7;
            int gr = row0 + r; if (gr >= N) gr = N - 1;
            float4 v = *reinterpret_cast<const float4*>(&x[(size_t)gr * D_DIM + k0 + cg * 4]);
            xs[(cg * 4 + 0) * XS_STRIDE + r] = v.x;
            xs[(cg * 4 + 1) * XS_STRIDE + r] = v.y;
            xs[(cg * 4 + 2) * XS_STRIDE + r] = v.z;
            xs[(cg * 4 + 3) * XS_STRIDE + r] = v.w;
        }
        // ---- load W tile: 128 experts x 32 k (1024 float4, 4 per thread) ----
        #pragma unroll
        for (int it = 0; it < 4; it++) {
            int f = tid + it * 256;
            int e = f >> 3, cg = f & 7;
            float4 v = *reinterpret_cast<const float4*>(&W[(size_t)e * D_DIM + k0 + cg * 4]);
            ws[(cg * 4 + 0) * WS_STRIDE + e] = v.x;
            ws[(cg * 4 + 1) * WS_STRIDE + e] = v.y;
            ws[(cg * 4 + 2) * WS_STRIDE + e] = v.z;
            ws[(cg * 4 + 3) * WS_STRIDE + e] = v.w;
        }
        __syncthreads();

        // ---- fresh per-tile partial sums (two-level accumulation: cuts the
        // 4096-term sequential rounding chain to 128 x 32-term chains) ----
        float part[8][4];
        #pragma unroll
        for (int i = 0; i < 8; i++)
            #pragma unroll
            for (int j = 0; j < 4; j++) part[i][j] = 0.f;

        #pragma unroll 8
        for (int kk = 0; kk < BK; kk++) {
            float4 a0 = *reinterpret_cast<const float4*>(&xs[kk * XS_STRIDE + ty * 8]);
            float4 a1 = *reinterpret_cast<const float4*>(&xs[kk * XS_STRIDE + ty * 8 + 4]);
            float4 b0 = *reinterpret_cast<const float4*>(&ws[kk * WS_STRIDE + tx * 4]);
            float a[8] = {a0.x, a0.y, a0.z, a0.w, a1.x, a1.y, a1.z, a1.w};
            float bb[4] = {b0.x, b0.y, b0.z, b0.w};
            #pragma unroll
            for (int i = 0; i < 8; i++)
                #pragma unroll
                for (int j = 0; j < 4; j++)
                    part[i][j] = fmaf(a[i], bb[j], part[i][j]);
        }
        #pragma unroll
        for (int i = 0; i < 8; i++)
            #pragma unroll
            for (int j = 0; j < 4; j++)
                acc[i][j] += part[i][j];
        __syncthreads();
    }

    // ---- bias add, spill logits to smem ----
    float4 bv = *reinterpret_cast<const float4*>(&bias[tx * 4]);
    float* lg = smem;  // [BM][LG_STRIDE], reuses GEMM smem (synced above)
    #pragma unroll
    for (int i = 0; i < 8; i++) {
        float4 v = make_float4(acc[i][0] + bv.x, acc[i][1] + bv.y,
                               acc[i][2] + bv.z, acc[i][3] + bv.w);
        *reinterpret_cast<float4*>(&lg[(ty * 8 + i) * LG_STRIDE + tx * 4]) = v;
    }
    __syncthreads();

    int ktop = 8;
    if (kptr) { int kv = *kptr; if (kv >= 1 && kv <= E_DIM) ktop = kv; }

    // ---- per-warp top-k threshold + softmax: warp ty owns rows ty*8..ty*8+7 ----
    for (int rr = 0; rr < 8; rr++) {
        int r = ty * 8 + rr;
        int grow = row0 + r;
        float4 vv = *reinterpret_cast<const float4*>(&lg[r * LG_STRIDE + tx * 4]);
        float v[4] = {vv.x, vv.y, vv.z, vv.w};
        unsigned msk = 0xF;
        float thr = -CUDART_INF_F;
        float rowmax = -CUDART_INF_F;
        for (int it = 0; it < ktop; it++) {
            float lm = -CUDART_INF_F; int lj = 0;
            #pragma unroll
            for (int j = 0; j < 4; j++)
                if (((msk >> j) & 1u) && v[j] > lm) { lm = v[j]; lj = j; }
            float wm = lm;
            #pragma unroll
            for (int off = 16; off; off >>= 1)
                wm = fmaxf(wm, __shfl_xor_sync(0xFFFFFFFFu, wm, off));
            unsigned bal = __ballot_sync(0xFFFFFFFFu, lm == wm);
            int src = __ffs(bal) - 1;
            if (tx == src) msk &= ~(1u << lj);
            if (it == 0) rowmax = wm;
            thr = wm;
        }
        float e[4]; float s = 0.f;
        #pragma unroll
        for (int j = 0; j < 4; j++) {
            e[j] = (v[j] >= thr) ? __expf(v[j] - rowmax) : 0.f;
            s += e[j];
        }
        #pragma unroll
        for (int off = 16; off; off >>= 1)
            s += __shfl_xor_sync(0xFFFFFFFFu, s, off);
        float inv = 1.f / s;
        if (grow < N) {
            float4 o = make_float4(e[0] * inv, e[1] * inv, e[2] * inv, e[3] * inv);
            *reinterpret_cast<float4*>(&out[(size_t)grow * E_DIM + tx * 4]) = o;
        }
    }
}

extern "C" void kernel_launch(void* const* d_in, const int* in_sizes, int n_in,
                              void* d_out, int out_size) {
    const float* x = (const float*)d_in[0];
    const float* W = (const float*)d_in[1];
    const float* b = (const float*)d_in[2];
    const int* kptr = (n_in > 3) ? (const int*)d_in[3] : nullptr;
    int N = out_size / E_DIM;
    int grid = (N + BM - 1) / BM;
    gating_fused<<<grid, 256>>>(x, W, b, kptr, (float*)d_out, N);
}

// round 9
// speedup vs baseline: 1.6034x; 1.6034x over previous
#include <cuda_runtime.h>
#include <cuda_bf16.h>
#include <cstdint>
#include <math_constants.h>

#define D_DIM 4096
#define E_DIM 128
#define BM 128
#define KBLK 32            // k16-steps per accumulation block (512 K)
#define NBLK 8             // 8 blocks * 512 = 4096
#define LG_STRIDE 132

__device__ __nv_bfloat16 g_wp[2][E_DIM * D_DIM];   // 2 MB static scratch: W hi/lo planes

__global__ void split_w(const float* __restrict__ W) {
    int i = blockIdx.x * blockDim.x + threadIdx.x;
    if (i >= E_DIM * D_DIM) return;
    float f = W[i];
    __nv_bfloat16 h = __float2bfloat16(f);
    g_wp[0][i] = h;
    g_wp[1][i] = __float2bfloat16(f - __bfloat162float(h));
}

__device__ __forceinline__ void mma16816(float* c, const uint32_t* a, const uint32_t* b) {
    asm volatile("mma.sync.aligned.m16n8k16.row.col.f32.bf16.bf16.f32 "
        "{%0,%1,%2,%3}, {%4,%5,%6,%7}, {%8,%9}, {%0,%1,%2,%3};"
        : "+f"(c[0]), "+f"(c[1]), "+f"(c[2]), "+f"(c[3])
        : "r"(a[0]), "r"(a[1]), "r"(a[2]), "r"(a[3]), "r"(b[0]), "r"(b[1]));
}

__device__ __forceinline__ void split2(float fx, float fy, uint32_t& hi, uint32_t& lo) {
    __nv_bfloat162 h = __floats2bfloat162_rn(fx, fy);
    float2 hf = __bfloat1622float2(h);
    __nv_bfloat162 l = __floats2bfloat162_rn(fx - hf.x, fy - hf.y);
    hi = *reinterpret_cast<uint32_t*>(&h);
    lo = *reinterpret_cast<uint32_t*>(&l);
}

__global__ __launch_bounds__(256, 1)
void gating_mma(const float* __restrict__ x, const float* __restrict__ bias,
                const int* __restrict__ kptr, float* __restrict__ out, int N)
{
    extern __shared__ float sm[];
    float* bs = sm;            // [128] bias
    float* lg = sm + 128;      // [128][132] logits

    const int tid = threadIdx.x;
    const int wid = tid >> 5, lid = tid & 31;
    const int wm = wid >> 2, wn = wid & 3;     // warp grid 2m x 4n
    const int gq = lid & 3, gr = lid >> 2;     // quad-id, group-row
    const int row0 = blockIdx.x * BM;

    if (tid < E_DIM) bs[tid] = bias[tid];

    // element offsets (relative to x + row0*D + gq*2) for the 8 A-fragment rows
    uint32_t aoff[8];
    #pragma unroll
    for (int mt = 0; mt < 4; mt++) {
        int r0 = wm * 64 + mt * 16 + gr;
        int r1 = r0 + 8;
        if (row0 + r0 >= N) r0 = N - 1 - row0;
        if (row0 + r1 >= N) r1 = N - 1 - row0;
        aoff[mt * 2]     = (uint32_t)r0 * D_DIM;
        aoff[mt * 2 + 1] = (uint32_t)r1 * D_DIM;
    }
    const float* xp = x + (size_t)row0 * D_DIM + gq * 2;
    const __nv_bfloat16* bp = &g_wp[0][(size_t)(wn * 32 + gr) * D_DIM + gq * 2];

    float mast[4][4][4];
    #pragma unroll
    for (int i = 0; i < 4; i++)
        #pragma unroll
        for (int j = 0; j < 4; j++)
            #pragma unroll
            for (int q = 0; q < 4; q++) mast[i][j][q] = 0.f;

    for (int kb = 0; kb < NBLK; kb++) {
        float C[4][4][4];
        #pragma unroll
        for (int i = 0; i < 4; i++)
            #pragma unroll
            for (int j = 0; j < 4; j++)
                #pragma unroll
                for (int q = 0; q < 4; q++) C[i][j][q] = 0.f;

        #pragma unroll 2
        for (int ks = 0; ks < KBLK; ks++) {
            // B fragments: hi/lo planes, 4 n-tiles
            uint32_t bh[4][2], bl[4][2];
            #pragma unroll
            for (int nt = 0; nt < 4; nt++) {
                const __nv_bfloat16* p = bp + nt * 8 * D_DIM;
                bh[nt][0] = *(const uint32_t*)(p);
                bh[nt][1] = *(const uint32_t*)(p + 8);
                bl[nt][0] = *(const uint32_t*)(p + E_DIM * D_DIM);
                bl[nt][1] = *(const uint32_t*)(p + E_DIM * D_DIM + 8);
            }
            // A fragments per m-tile: load fp32, split to bf16 hi/lo, 4x4 MMA
            #pragma unroll
            for (int mt = 0; mt < 4; mt++) {
                float2 v0 = *(const float2*)(xp + aoff[mt * 2]);
                float2 v1 = *(const float2*)(xp + aoff[mt * 2 + 1]);
                float2 v2 = *(const float2*)(xp + aoff[mt * 2] + 8);
                float2 v3 = *(const float2*)(xp + aoff[mt * 2 + 1] + 8);
                uint32_t ah[4], al[4];
                split2(v0.x, v0.y, ah[0], al[0]);
                split2(v1.x, v1.y, ah[1], al[1]);
                split2(v2.x, v2.y, ah[2], al[2]);
                split2(v3.x, v3.y, ah[3], al[3]);
                #pragma unroll
                for (int nt = 0; nt < 4; nt++) {
                    mma16816(C[mt][nt], ah, bh[nt]);
                    mma16816(C[mt][nt], al, bh[nt]);
                    mma16816(C[mt][nt], ah, bl[nt]);
                    mma16816(C[mt][nt], al, bl[nt]);
                }
            }
            xp += 16;
            bp += 16;
        }
        #pragma unroll
        for (int i = 0; i < 4; i++)
            #pragma unroll
            for (int j = 0; j < 4; j++)
                #pragma unroll
                for (int q = 0; q < 4; q++) mast[i][j][q] += C[i][j][q];
    }

    __syncthreads();   // bias writes visible; smem free for logits

    // ---- write logits + bias to smem ----
    #pragma unroll
    for (int mt = 0; mt < 4; mt++) {
        #pragma unroll
        for (int nt = 0; nt < 4; nt++) {
            int rr = wm * 64 + mt * 16 + gr;
            int cc = wn * 32 + nt * 8 + gq * 2;
            lg[rr * LG_STRIDE + cc]           = mast[mt][nt][0] + bs[cc];
            lg[rr * LG_STRIDE + cc + 1]       = mast[mt][nt][1] + bs[cc + 1];
            lg[(rr + 8) * LG_STRIDE + cc]     = mast[mt][nt][2] + bs[cc];
            lg[(rr + 8) * LG_STRIDE + cc + 1] = mast[mt][nt][3] + bs[cc + 1];
        }
    }
    __syncthreads();

    int ktop = 8;
    if (kptr) { int kv = *kptr; if (kv >= 1 && kv <= E_DIM) ktop = kv; }

    // ---- per-warp top-k threshold + softmax: warp wid owns rows wid*16..+15 ----
    const int tx = lid;
    for (int rr2 = 0; rr2 < 16; rr2++) {
        int rrow = wid * 16 + rr2;
        int go = row0 + rrow;
        float4 vv = *reinterpret_cast<const float4*>(&lg[rrow * LG_STRIDE + tx * 4]);
        float v[4] = {vv.x, vv.y, vv.z, vv.w};
        unsigned msk = 0xF;
        float thr = -CUDART_INF_F, rowmax = -CUDART_INF_F;
        for (int it = 0; it < ktop; it++) {
            float lm = -CUDART_INF_F; int lj = 0;
            #pragma unroll
            for (int j = 0; j < 4; j++)
                if (((msk >> j) & 1u) && v[j] > lm) { lm = v[j]; lj = j; }
            float wm2 = lm;
            #pragma unroll
            for (int off = 16; off; off >>= 1)
                wm2 = fmaxf(wm2, __shfl_xor_sync(0xFFFFFFFFu, wm2, off));
            unsigned bal = __ballot_sync(0xFFFFFFFFu, lm == wm2);
            int src = __ffs(bal) - 1;
            if (tx == src) msk &= ~(1u << lj);
            if (it == 0) rowmax = wm2;
            thr = wm2;
        }
        float e[4]; float s = 0.f;
        #pragma unroll
        for (int j = 0; j < 4; j++) {
            e[j] = (v[j] >= thr) ? __expf(v[j] - rowmax) : 0.f;
            s += e[j];
        }
        #pragma unroll
        for (int off = 16; off; off >>= 1)
            s += __shfl_xor_sync(0xFFFFFFFFu, s, off);
        float inv = 1.f / s;
        if (go < N) {
            float4 o = make_float4(e[0] * inv, e[1] * inv, e[2] * inv, e[3] * inv);
            *reinterpret_cast<float4*>(&out[(size_t)go * E_DIM + tx * 4]) = o;
        }
    }
}

extern "C" void kernel_launch(void* const* d_in, const int* in_sizes, int n_in,
                              void* d_out, int out_size) {
    const float* x = (const float*)d_in[0];
    const float* W = (const float*)d_in[1];
    const float* b = (const float*)d_in[2];
    const int* kptr = (n_in > 3) ? (const int*)d_in[3] : nullptr;
    int N = out_size / E_DIM;

    const int smem_bytes = (128 + BM * LG_STRIDE) * (int)sizeof(float);   // 68096
    cudaFuncSetAttribute(gating_mma, cudaFuncAttributeMaxDynamicSharedMemorySize, smem_bytes);

    split_w<<<(E_DIM * D_DIM + 255) / 256, 256>>>(W);
    int grid = (N + BM - 1) / BM;
    gating_mma<<<grid, 256, smem_bytes>>>(x, b, kptr, (float*)d_out, N);
}

// round 17
// speedup vs baseline: 2.3352x; 1.4564x over previous
#include <cuda_runtime.h>
#include <cuda_bf16.h>
#include <cstdint>
#include <math_constants.h>

#define D_DIM 4096
#define E_DIM 128
#define BM 128
#define BK 32
#define NC (D_DIM / BK)       // 128 chunks
#define LG_STRIDE 132

#define ROWB 80               // staged row stride bytes (64B data + 16B pad)
#define PLANE_B (128 * ROWB)  // 10240
#define BUF_B (4 * PLANE_B)   // 40960: [Ahi, Alo, Bhi, Blo]
#define SM_BIAS_OFF (2 * BUF_B)          // 81920
#define SMEM_DYN (SM_BIAS_OFF + 512)     // 82432

__device__ __nv_bfloat16 g_wp[2][E_DIM * D_DIM];   // W hi/lo planes (2 MB)

__global__ void split_w(const float* __restrict__ W) {
    int i = blockIdx.x * blockDim.x + threadIdx.x;
    if (i >= E_DIM * D_DIM) return;
    float f = W[i];
    __nv_bfloat16 h = __float2bfloat16(f);
    g_wp[0][i] = h;
    g_wp[1][i] = __float2bfloat16(f - __bfloat162float(h));
}

__device__ __forceinline__ uint32_t smem_u32(const void* p) {
    uint32_t a;
    asm("{ .reg .u64 t; cvta.to.shared.u64 t, %1; cvt.u32.u64 %0, t; }" : "=r"(a) : "l"(p));
    return a;
}
__device__ __forceinline__ void mma16816(float* c, const uint32_t* a, const uint32_t* b) {
    asm volatile("mma.sync.aligned.m16n8k16.row.col.f32.bf16.bf16.f32 "
        "{%0,%1,%2,%3}, {%4,%5,%6,%7}, {%8,%9}, {%0,%1,%2,%3};"
        : "+f"(c[0]), "+f"(c[1]), "+f"(c[2]), "+f"(c[3])
        : "r"(a[0]), "r"(a[1]), "r"(a[2]), "r"(a[3]), "r"(b[0]), "r"(b[1]));
}
#define LDSM4(r0, r1, r2, r3, addr) \
    asm volatile("ldmatrix.sync.aligned.m8n8.x4.shared.b16 {%0,%1,%2,%3}, [%4];" \
        : "=r"(r0), "=r"(r1), "=r"(r2), "=r"(r3) : "r"(addr))
#define CPASYNC16(dst, src) \
    asm volatile("cp.async.cg.shared.global [%0], [%1], 16;" :: "r"(dst), "l"(src))
#define CPCOMMIT() asm volatile("cp.async.commit_group;" ::: "memory")
#define CPWAIT0()  asm volatile("cp.async.wait_group 0;" ::: "memory")

__device__ __forceinline__ void split2(float fx, float fy, uint32_t& hi, uint32_t& lo) {
    __nv_bfloat162 h = __floats2bfloat162_rn(fx, fy);
    float2 hf = __bfloat1622float2(h);
    __nv_bfloat162 l = __floats2bfloat162_rn(fx - hf.x, fy - hf.y);
    hi = *reinterpret_cast<uint32_t*>(&h);
    lo = *reinterpret_cast<uint32_t*>(&l);
}

__global__ __launch_bounds__(256, 1)
void gating_mma(const float* __restrict__ x, const float* __restrict__ bias,
                const int* __restrict__ kptr, float* __restrict__ out, int N)
{
    extern __shared__ char smc[];
    const uint32_t sb = smem_u32(smc);
    float* bs = (float*)(smc + SM_BIAS_OFF);
    float* lg = (float*)smc;              // logits reuse stage buffers post-loop

    const int tid = threadIdx.x;
    const int wid = tid >> 5, lid = tid & 31;
    const int wm = wid >> 2, wn = wid & 3;     // 2m x 4n warp grid
    const int gq = lid & 3, gr = lid >> 2;
    const int row0 = blockIdx.x * BM;

    if (tid < E_DIM) bs[tid] = bias[tid];

    // ---- staging indices ----
    const int arow = tid >> 1, ahalf = tid & 1;   // A: thread loads 16 floats of row arow
    int gxr = row0 + arow; if (gxr >= N) gxr = N - 1;
    const float* xsrc = x + (size_t)gxr * D_DIM + ahalf * 16;
    const uint32_t adst = sb + arow * ROWB + ahalf * 32;   // + buf*BUF_B + plane*PLANE_B

    // B: 4 cp.async per thread: idx -> (plane, e, seg)
    uint32_t bdst[4]; const __nv_bfloat16* bsrc[4];
    #pragma unroll
    for (int i = 0; i < 4; i++) {
        int idx = tid + i * 256;
        int p = idx >> 9, rem = idx & 511, e = rem >> 2, seg = rem & 3;
        bdst[i] = sb + 2 * PLANE_B + p * PLANE_B + e * ROWB + seg * 16;
        bsrc[i] = &g_wp[p][(size_t)e * D_DIM + seg * 8];
    }

    // ---- ldmatrix addresses (chunk-invariant parts) ----
    uint32_t a_ld[4];
    #pragma unroll
    for (int mt = 0; mt < 4; mt++)
        a_ld[mt] = sb + (wm * 64 + mt * 16 + (lid & 15)) * ROWB + ((lid & 16) ? 16 : 0);
    uint32_t b_ld[2];
    #pragma unroll
    for (int ntp = 0; ntp < 2; ntp++)
        b_ld[ntp] = sb + 2 * PLANE_B +
                    (wn * 32 + ntp * 16 + (lid & 7) + ((lid & 16) ? 8 : 0)) * ROWB +
                    ((lid & 8) ? 16 : 0);

    float mast[4][4][4], C[4][4][4];
    #pragma unroll
    for (int i = 0; i < 4; i++)
        #pragma unroll
        for (int j = 0; j < 4; j++)
            #pragma unroll
            for (int q = 0; q < 4; q++) { mast[i][j][q] = 0.f; C[i][j][q] = 0.f; }

    // ---- prologue: stage chunk 0 into buf 0 ----
    {
        #pragma unroll
        for (int i = 0; i < 4; i++) CPASYNC16(bdst[i], bsrc[i]);
        CPCOMMIT();
        float4 xf[4];
        #pragma unroll
        for (int i = 0; i < 4; i++) xf[i] = *reinterpret_cast<const float4*>(xsrc + i * 4);
        uint32_t hi[8], lo[8];
        #pragma unroll
        for (int i = 0; i < 4; i++) {
            split2(xf[i].x, xf[i].y, hi[2 * i], lo[2 * i]);
            split2(xf[i].z, xf[i].w, hi[2 * i + 1], lo[2 * i + 1]);
        }
        *(uint4*)(smc + (adst - sb))      = make_uint4(hi[0], hi[1], hi[2], hi[3]);
        *(uint4*)(smc + (adst - sb) + 16) = make_uint4(hi[4], hi[5], hi[6], hi[7]);
        *(uint4*)(smc + (adst - sb) + PLANE_B)      = make_uint4(lo[0], lo[1], lo[2], lo[3]);
        *(uint4*)(smc + (adst - sb) + PLANE_B + 16) = make_uint4(lo[4], lo[5], lo[6], lo[7]);
        CPWAIT0();
        __syncthreads();
    }

    for (int c = 0; c < NC; c++) {
        const uint32_t cb = (uint32_t)(c & 1) * BUF_B;
        const uint32_t nb = (uint32_t)(~c & 1) * BUF_B;
        const bool pf = (c + 1 < NC);

        float4 xf[4];
        if (pf) {
            const int k0 = (c + 1) * BK;
            #pragma unroll
            for (int i = 0; i < 4; i++) CPASYNC16(bdst[i] + nb, bsrc[i] + k0);
            CPCOMMIT();
            #pragma unroll
            for (int i = 0; i < 4; i++)
                xf[i] = *reinterpret_cast<const float4*>(xsrc + k0 + i * 4);
        }

        // ---- compute chunk c from buf cb: 2 k16-steps ----
        #pragma unroll
        for (int s = 0; s < 2; s++) {
            uint32_t bh[4][2], bl[4][2];
            #pragma unroll
            for (int ntp = 0; ntp < 2; ntp++) {
                uint32_t ba = b_ld[ntp] + cb + s * 32;
                LDSM4(bh[ntp * 2][0], bh[ntp * 2][1], bh[ntp * 2 + 1][0], bh[ntp * 2 + 1][1], ba);
                LDSM4(bl[ntp * 2][0], bl[ntp * 2][1], bl[ntp * 2 + 1][0], bl[ntp * 2 + 1][1], ba + PLANE_B);
            }
            #pragma unroll
            for (int mt = 0; mt < 4; mt++) {
                uint32_t ah[4], al[4];
                uint32_t aa = a_ld[mt] + cb + s * 32;
                LDSM4(ah[0], ah[1], ah[2], ah[3], aa);
                LDSM4(al[0], al[1], al[2], al[3], aa + PLANE_B);
                #pragma unroll
                for (int nt = 0; nt < 4; nt++) {
                    mma16816(C[mt][nt], ah, bh[nt]);
                    mma16816(C[mt][nt], al, bh[nt]);
                    mma16816(C[mt][nt], ah, bl[nt]);
                    mma16816(C[mt][nt], al, bl[nt]);
                }
            }
        }

        if (pf) {
            uint32_t hi[8], lo[8];
            #pragma unroll
            for (int i = 0; i < 4; i++) {
                split2(xf[i].x, xf[i].y, hi[2 * i], lo[2 * i]);
                split2(xf[i].z, xf[i].w, hi[2 * i + 1], lo[2 * i + 1]);
            }
            char* ad = smc + (adst - sb) + nb;
            *(uint4*)(ad)                 = make_uint4(hi[0], hi[1], hi[2], hi[3]);
            *(uint4*)(ad + 16)            = make_uint4(hi[4], hi[5], hi[6], hi[7]);
            *(uint4*)(ad + PLANE_B)       = make_uint4(lo[0], lo[1], lo[2], lo[3]);
            *(uint4*)(ad + PLANE_B + 16)  = make_uint4(lo[4], lo[5], lo[6], lo[7]);
            CPWAIT0();
        }
        __syncthreads();

        // two-level accumulation: drain every 16 chunks (512 K)
        if ((c & 15) == 15) {
            #pragma unroll
            for (int i = 0; i < 4; i++)
                #pragma unroll
                for (int j = 0; j < 4; j++)
                    #pragma unroll
                    for (int q = 0; q < 4; q++) { mast[i][j][q] += C[i][j][q]; C[i][j][q] = 0.f; }
        }
    }

    // ---- logits + bias -> smem (reuses stage buffers; all reads done) ----
    #pragma unroll
    for (int mt = 0; mt < 4; mt++) {
        #pragma unroll
        for (int nt = 0; nt < 4; nt++) {
            int rr = wm * 64 + mt * 16 + gr;
            int cc = wn * 32 + nt * 8 + gq * 2;
            lg[rr * LG_STRIDE + cc]           = mast[mt][nt][0] + bs[cc];
            lg[rr * LG_STRIDE + cc + 1]       = mast[mt][nt][1] + bs[cc + 1];
            lg[(rr + 8) * LG_STRIDE + cc]     = mast[mt][nt][2] + bs[cc];
            lg[(rr + 8) * LG_STRIDE + cc + 1] = mast[mt][nt][3] + bs[cc + 1];
        }
    }
    __syncthreads();

    int ktop = 8;
    if (kptr) { int kv = *kptr; if (kv >= 1 && kv <= E_DIM) ktop = kv; }

    const int tx = lid;
    for (int rr2 = 0; rr2 < 16; rr2++) {
        int rrow = wid * 16 + rr2;
        int go = row0 + rrow;
        float4 vv = *reinterpret_cast<const float4*>(&lg[rrow * LG_STRIDE + tx * 4]);
        float v[4] = {vv.x, vv.y, vv.z, vv.w};
        unsigned msk = 0xF;
        float thr = -CUDART_INF_F, rowmax = -CUDART_INF_F;
        for (int it = 0; it < ktop; it++) {
            float lm = -CUDART_INF_F; int lj = 0;
            #pragma unroll
            for (int j = 0; j < 4; j++)
                if (((msk >> j) & 1u) && v[j] > lm) { lm = v[j]; lj = j; }
            float wm2 = lm;
            #pragma unroll
            for (int off = 16; off; off >>= 1)
                wm2 = fmaxf(wm2, __shfl_xor_sync(0xFFFFFFFFu, wm2, off));
            unsigned bal = __ballot_sync(0xFFFFFFFFu, lm == wm2);
            int src = __ffs(bal) - 1;
            if (tx == src) msk &= ~(1u << lj);
            if (it == 0) rowmax = wm2;
            thr = wm2;
        }
        float e[4]; float s = 0.f;
        #pragma unroll
        for (int j = 0; j < 4; j++) {
            e[j] = (v[j] >= thr) ? __expf(v[j] - rowmax) : 0.f;
            s += e[j];
        }
        #pragma unroll
        for (int off = 16; off; off >>= 1)
            s += __shfl_xor_sync(0xFFFFFFFFu, s, off);
        float inv = 1.f / s;
        if (go < N) {
            float4 o = make_float4(e[0] * inv, e[1] * inv, e[2] * inv, e[3] * inv);
            *reinterpret_cast<float4*>(&out[(size_t)go * E_DIM + tx * 4]) = o;
        }
    }
}

extern "C" void kernel_launch(void* const* d_in, const int* in_sizes, int n_in,
                              void* d_out, int out_size) {
    const float* x = (const float*)d_in[0];
    const float* W = (const float*)d_in[1];
    const float* b = (const float*)d_in[2];
    const int* kptr = (n_in > 3) ? (const int*)d_in[3] : nullptr;
    int N = out_size / E_DIM;

    cudaFuncSetAttribute(gating_mma, cudaFuncAttributeMaxDynamicSharedMemorySize, SMEM_DYN);

    split_w<<<(E_DIM * D_DIM + 255) / 256, 256>>>(W);
    int grid = (N + BM - 1) / BM;
    gating_mma<<<grid, 256, SMEM_DYN>>>(x, b, kptr, (float*)d_out, N);
}